// round 1
// baseline (speedup 1.0000x reference)
#include <cuda_runtime.h>
#include <float.h>
#include <stdint.h>

// Problem constants
#define Bsz 16
#define Npt 4096
#define Cft 64
#define Mc  1024
#define Kn  64
#define Hd  128
#define CIN 67   // C+3

// ---------------- scratch (device globals; no allocation allowed) --------
__device__ int   g_idx[Bsz*Mc];
__device__ int   g_nbr[Bsz*Mc*Kn];
__device__ int   g_cnt[Bsz*Mc];
__device__ float g_ctr[Bsz*Mc*3];
__device__ float g_poss_dump[Bsz*Mc*3];  // fallback if out buffer has no pos_s region

// ---------------- f32x2 helpers ------------------------------------------
__device__ __forceinline__ unsigned long long fma2(unsigned long long a,
                                                   unsigned long long b,
                                                   unsigned long long c) {
    unsigned long long d;
    asm("fma.rn.f32x2 %0, %1, %2, %3;" : "=l"(d) : "l"(a), "l"(b), "l"(c));
    return d;
}
__device__ __forceinline__ unsigned long long dup2(float x) {
    unsigned long long d;
    unsigned xi = __float_as_uint(x);
    asm("mov.b64 %0, {%1, %2};" : "=l"(d) : "r"(xi), "r"(xi));
    return d;
}
__device__ __forceinline__ void unpk(unsigned long long v, float& lo, float& hi) {
    unsigned a, b;
    asm("mov.b64 {%0, %1}, %2;" : "=r"(a), "=r"(b) : "l"(v));
    lo = __uint_as_float(a);
    hi = __uint_as_float(b);
}

// ============================ 1) FPS ======================================
// One block per batch. Coordinates + running min-dists live in registers.
// Matches jnp semantics: dists=min(dists,d); argmax (first index wins).
// Non-fused mul/add order: ((dx*dx + dy*dy) + dz*dz).
#define FPS_T 256
#define PPT (Npt / FPS_T)  // 16

__global__ __launch_bounds__(FPS_T) void fps_kernel(const float* __restrict__ pos) {
    int b = blockIdx.x;
    const float* p = pos + b * Npt * 3;
    int t = threadIdx.x;

    float px[PPT], py[PPT], pz[PPT], dd[PPT];
#pragma unroll
    for (int j = 0; j < PPT; j++) {
        int i = t + j * FPS_T;
        px[j] = p[i * 3 + 0];
        py[j] = p[i * 3 + 1];
        pz[j] = p[i * 3 + 2];
        dd[j] = FLT_MAX;
    }

    __shared__ float swv[FPS_T / 32];
    __shared__ int   swi[FPS_T / 32];
    __shared__ int   s_last;

    if (t == 0) g_idx[b * Mc] = 0;
    int last = 0;

    for (int s = 1; s < Mc; s++) {
        float lx = __ldg(p + last * 3 + 0);
        float ly = __ldg(p + last * 3 + 1);
        float lz = __ldg(p + last * 3 + 2);
        float bv = -1.0f;
        int   bi = 0x7fffffff;
#pragma unroll
        for (int j = 0; j < PPT; j++) {
            float dx = __fsub_rn(px[j], lx);
            float dy = __fsub_rn(py[j], ly);
            float dz = __fsub_rn(pz[j], lz);
            float d  = __fadd_rn(__fadd_rn(__fmul_rn(dx, dx), __fmul_rn(dy, dy)),
                                 __fmul_rn(dz, dz));
            float v = fminf(dd[j], d);
            dd[j]   = v;
            int i   = t + j * FPS_T;
            if (v > bv || (v == bv && i < bi)) { bv = v; bi = i; }
        }
        // warp reduce (first-index tie-break)
#pragma unroll
        for (int off = 16; off > 0; off >>= 1) {
            float ov = __shfl_down_sync(0xffffffffu, bv, off);
            int   oi = __shfl_down_sync(0xffffffffu, bi, off);
            if (ov > bv || (ov == bv && oi < bi)) { bv = ov; bi = oi; }
        }
        int w = t >> 5;
        if ((t & 31) == 0) { swv[w] = bv; swi[w] = bi; }
        __syncthreads();
        if (t < 32) {
            bv = (t < FPS_T / 32) ? swv[t] : -1.0f;
            bi = (t < FPS_T / 32) ? swi[t] : 0x7fffffff;
#pragma unroll
            for (int off = 4; off > 0; off >>= 1) {
                float ov = __shfl_down_sync(0xffffffffu, bv, off);
                int   oi = __shfl_down_sync(0xffffffffu, bi, off);
                if (ov > bv || (ov == bv && oi < bi)) { bv = ov; bi = oi; }
            }
            if (t == 0) { g_idx[b * Mc + s] = bi; s_last = bi; }
        }
        __syncthreads();
        last = s_last;
    }
}

// ============================ 2) radius query =============================
// One warp per center: first Kn in-radius neighbors in index order.
// d2 = (sn + pn) - 2*dot, all non-fused (matches reference formula shape).
#define QWARPS 8

__global__ __launch_bounds__(QWARPS * 32) void query_kernel(
    const float* __restrict__ pos, float* __restrict__ poss_out) {
    int cm   = blockIdx.x * QWARPS + (threadIdx.x >> 5);
    int lane = threadIdx.x & 31;
    int b    = cm >> 10;  // cm / Mc
    const float* p = pos + b * Npt * 3;

    int   ci = g_idx[cm];
    float sx = p[ci * 3 + 0], sy = p[ci * 3 + 1], sz = p[ci * 3 + 2];
    if (lane == 0) {
        poss_out[cm * 3 + 0] = sx;
        poss_out[cm * 3 + 1] = sy;
        poss_out[cm * 3 + 2] = sz;
        g_ctr[cm * 3 + 0] = sx;
        g_ctr[cm * 3 + 1] = sy;
        g_ctr[cm * 3 + 2] = sz;
    }
    float sn = __fadd_rn(__fadd_rn(__fmul_rn(sx, sx), __fmul_rn(sy, sy)),
                         __fmul_rn(sz, sz));
    const float R2 = 0.2f * 0.2f;

    int cnt = 0;
    for (int base = 0; base < Npt; base += 32) {
        int   i = base + lane;
        float xx = p[i * 3 + 0], yy = p[i * 3 + 1], zz = p[i * 3 + 2];
        float pn = __fadd_rn(__fadd_rn(__fmul_rn(xx, xx), __fmul_rn(yy, yy)),
                             __fmul_rn(zz, zz));
        float dot = __fadd_rn(__fadd_rn(__fmul_rn(sx, xx), __fmul_rn(sy, yy)),
                              __fmul_rn(sz, zz));
        float d2 = __fsub_rn(__fadd_rn(sn, pn), __fmul_rn(2.0f, dot));
        bool  in = (d2 <= R2);
        unsigned ball = __ballot_sync(0xffffffffu, in);
        if (in) {
            int ppos = cnt + __popc(ball & ((1u << lane) - 1u));
            if (ppos < Kn) g_nbr[cm * Kn + ppos] = i;
        }
        cnt += __popc(ball);
        if (cnt >= Kn) break;
    }
    if (cnt > Kn) cnt = Kn;
    for (int k = cnt + lane; k < Kn; k += 32) g_nbr[cm * Kn + k] = 0;
    if (lane == 0) g_cnt[cm] = cnt;
}

// ============================ 3) MLP + masked max =========================
// Persistent blocks (1/SM). Weights staged to smem once. Per center:
// gather feat^T [67][64] -> layer1 GEMM 64x128 (f32x2) -> h1 [64][132]
// -> layer2 GEMM 64x128 -> relu -> masked max over k -> out row.
#define MLP_T 256
#define LDK 68    // featT row pitch (floats), 16B-aligned rows
#define LDH 132   // h1 row pitch (floats), 16B-aligned rows

#define SMEM_FLOATS (CIN*Hd + Hd*Hd + Hd + Hd + CIN*LDK + Kn*LDH + 16*Hd)
#define SMEM_BYTES  (SMEM_FLOATS * 4 + Kn * 4)

extern __shared__ float smem[];

__global__ __launch_bounds__(MLP_T, 1) void mlp_kernel(
    const float* __restrict__ x, const float* __restrict__ pos,
    const float* __restrict__ W1, const float* __restrict__ b1,
    const float* __restrict__ W2, const float* __restrict__ b2,
    float* __restrict__ out) {
    float* W1s   = smem;                   // 67*128
    float* W2s   = W1s + CIN * Hd;         // 128*128
    float* b1s   = W2s + Hd * Hd;          // 128
    float* b2s   = b1s + Hd;               // 128
    float* featT = b2s + Hd;               // 67*68
    float* h1s   = featT + CIN * LDK;      // 64*132
    float* smax  = h1s + Kn * LDH;         // 16*128
    int*   snbr  = (int*)(smax + 16 * Hd); // 64
    __shared__ int s_cnt;

    int tid = threadIdx.x;
    for (int i = tid; i < CIN * Hd; i += MLP_T) W1s[i] = W1[i];
    for (int i = tid; i < Hd * Hd; i += MLP_T) W2s[i] = W2[i];
    if (tid < Hd) { b1s[tid] = b1[tid]; b2s[tid] = b2[tid]; }

    int ty   = tid >> 4;
    int tx   = tid & 15;
    int row0 = ty * 4;

    for (int cm = blockIdx.x; cm < Bsz * Mc; cm += gridDim.x) {
        int b = cm >> 10;
        __syncthreads();  // weights ready (1st iter) / previous center done
        if (tid < Kn) snbr[tid] = g_nbr[cm * Kn + tid];
        if (tid == 0) s_cnt = g_cnt[cm];
        __syncthreads();
        int cnt = s_cnt;

        // gather x features -> featT[c][k]
        const float* xb = x + (size_t)b * Npt * Cft;
        for (int j = tid; j < Kn * Cft; j += MLP_T) {
            int k = j >> 6, c = j & 63;
            featT[c * LDK + k] = xb[(size_t)snbr[k] * Cft + c];
        }
        // pos diffs -> featT[64..66][k]
        float cx = g_ctr[cm * 3 + 0], cy = g_ctr[cm * 3 + 1], cz = g_ctr[cm * 3 + 2];
        const float* pb = pos + b * Npt * 3;
        for (int j = tid; j < Kn * 3; j += MLP_T) {
            int   k  = j & 63, d = j >> 6;
            float pv = pb[snbr[k] * 3 + d];
            float c0 = (d == 0) ? cx : ((d == 1) ? cy : cz);
            featT[(Cft + d) * LDK + k] = pv - c0;
        }
        __syncthreads();

        unsigned long long acc[4][4];
#pragma unroll
        for (int r = 0; r < 4; r++)
#pragma unroll
            for (int q = 0; q < 4; q++) acc[r][q] = 0ULL;

        // -------- layer 1: feat[64x67] @ W1[67x128] ----------
        if (row0 < cnt) {
            for (int c = 0; c < CIN; c++) {
                float4 av = *(const float4*)(featT + c * LDK + row0);
                const unsigned long long* bp =
                    (const unsigned long long*)(W1s + c * Hd + tx * 8);
                unsigned long long bb0 = bp[0], bb1 = bp[1], bb2 = bp[2], bb3 = bp[3];
                unsigned long long a0 = dup2(av.x), a1 = dup2(av.y),
                                   a2 = dup2(av.z), a3 = dup2(av.w);
                acc[0][0] = fma2(a0, bb0, acc[0][0]); acc[0][1] = fma2(a0, bb1, acc[0][1]);
                acc[0][2] = fma2(a0, bb2, acc[0][2]); acc[0][3] = fma2(a0, bb3, acc[0][3]);
                acc[1][0] = fma2(a1, bb0, acc[1][0]); acc[1][1] = fma2(a1, bb1, acc[1][1]);
                acc[1][2] = fma2(a1, bb2, acc[1][2]); acc[1][3] = fma2(a1, bb3, acc[1][3]);
                acc[2][0] = fma2(a2, bb0, acc[2][0]); acc[2][1] = fma2(a2, bb1, acc[2][1]);
                acc[2][2] = fma2(a2, bb2, acc[2][2]); acc[2][3] = fma2(a2, bb3, acc[2][3]);
                acc[3][0] = fma2(a3, bb0, acc[3][0]); acc[3][1] = fma2(a3, bb1, acc[3][1]);
                acc[3][2] = fma2(a3, bb2, acc[3][2]); acc[3][3] = fma2(a3, bb3, acc[3][3]);
            }
            // bias + relu + store h1
#pragma unroll
            for (int r = 0; r < 4; r++) {
                float f0l, f0h, f1l, f1h, f2l, f2h, f3l, f3h;
                unpk(acc[r][0], f0l, f0h); unpk(acc[r][1], f1l, f1h);
                unpk(acc[r][2], f2l, f2h); unpk(acc[r][3], f3l, f3h);
                int    col = tx * 8;
                float4 v0, v1;
                v0.x = fmaxf(f0l + b1s[col + 0], 0.f);
                v0.y = fmaxf(f0h + b1s[col + 1], 0.f);
                v0.z = fmaxf(f1l + b1s[col + 2], 0.f);
                v0.w = fmaxf(f1h + b1s[col + 3], 0.f);
                v1.x = fmaxf(f2l + b1s[col + 4], 0.f);
                v1.y = fmaxf(f2h + b1s[col + 5], 0.f);
                v1.z = fmaxf(f3l + b1s[col + 6], 0.f);
                v1.w = fmaxf(f3h + b1s[col + 7], 0.f);
                *(float4*)(h1s + (row0 + r) * LDH + col)     = v0;
                *(float4*)(h1s + (row0 + r) * LDH + col + 4) = v1;
            }
        }
        __syncthreads();

        // -------- layer 2: h1[64x128] @ W2[128x128] ----------
#pragma unroll
        for (int r = 0; r < 4; r++)
#pragma unroll
            for (int q = 0; q < 4; q++) acc[r][q] = 0ULL;

        if (row0 < cnt) {
            for (int h = 0; h < Hd; h++) {
                unsigned long long a0 = dup2(h1s[(row0 + 0) * LDH + h]);
                unsigned long long a1 = dup2(h1s[(row0 + 1) * LDH + h]);
                unsigned long long a2 = dup2(h1s[(row0 + 2) * LDH + h]);
                unsigned long long a3 = dup2(h1s[(row0 + 3) * LDH + h]);
                const unsigned long long* bp =
                    (const unsigned long long*)(W2s + h * Hd + tx * 8);
                unsigned long long bb0 = bp[0], bb1 = bp[1], bb2 = bp[2], bb3 = bp[3];
                acc[0][0] = fma2(a0, bb0, acc[0][0]); acc[0][1] = fma2(a0, bb1, acc[0][1]);
                acc[0][2] = fma2(a0, bb2, acc[0][2]); acc[0][3] = fma2(a0, bb3, acc[0][3]);
                acc[1][0] = fma2(a1, bb0, acc[1][0]); acc[1][1] = fma2(a1, bb1, acc[1][1]);
                acc[1][2] = fma2(a1, bb2, acc[1][2]); acc[1][3] = fma2(a1, bb3, acc[1][3]);
                acc[2][0] = fma2(a2, bb0, acc[2][0]); acc[2][1] = fma2(a2, bb1, acc[2][1]);
                acc[2][2] = fma2(a2, bb2, acc[2][2]); acc[2][3] = fma2(a2, bb3, acc[2][3]);
                acc[3][0] = fma2(a3, bb0, acc[3][0]); acc[3][1] = fma2(a3, bb1, acc[3][1]);
                acc[3][2] = fma2(a3, bb2, acc[3][2]); acc[3][3] = fma2(a3, bb3, acc[3][3]);
            }
        }

        // -------- bias + relu + masked max over k ----------
        float cmax[8];
#pragma unroll
        for (int q = 0; q < 8; q++) cmax[q] = -1e30f;
        if (row0 < cnt) {
            int rmax = cnt - row0;
            if (rmax > 4) rmax = 4;
            for (int r = 0; r < rmax; r++) {
                float vals[8];
                unpk(acc[r][0], vals[0], vals[1]);
                unpk(acc[r][1], vals[2], vals[3]);
                unpk(acc[r][2], vals[4], vals[5]);
                unpk(acc[r][3], vals[6], vals[7]);
#pragma unroll
                for (int q = 0; q < 8; q++) {
                    float hv = fmaxf(vals[q] + b2s[tx * 8 + q], 0.f);
                    cmax[q]  = fmaxf(cmax[q], hv);
                }
            }
        }
#pragma unroll
        for (int q = 0; q < 8; q++) smax[ty * Hd + tx * 8 + q] = cmax[q];
        __syncthreads();
        if (tid < Hd) {
            float mv = -1e30f;
#pragma unroll
            for (int yy = 0; yy < 16; yy++) mv = fmaxf(mv, smax[yy * Hd + tid]);
            out[(size_t)cm * Hd + tid] = (cnt > 0) ? mv : 0.0f;
        }
    }
}

// ============================ launch ======================================
extern "C" void kernel_launch(void* const* d_in, const int* in_sizes, int n_in,
                              void* d_out, int out_size) {
    const float* x   = (const float*)d_in[0];
    const float* pos = (const float*)d_in[1];
    const float* W1  = (const float*)d_in[2];
    const float* b1  = (const float*)d_in[3];
    const float* W2  = (const float*)d_in[4];
    const float* b2  = (const float*)d_in[5];
    float* out = (float*)d_out;

    // tuple output layout: out [B*M*H] then pos_s [B*M*3]; guard against
    // a layout mismatch so we never write OOB.
    float* poss;
    if (out_size >= Bsz * Mc * (Hd + 3)) {
        poss = out + (size_t)Bsz * Mc * Hd;
    } else {
        void* tmp = nullptr;
        cudaGetSymbolAddress(&tmp, g_poss_dump);
        poss = (float*)tmp;
    }

    cudaFuncSetAttribute(mlp_kernel, cudaFuncAttributeMaxDynamicSharedMemorySize,
                         SMEM_BYTES);

    fps_kernel<<<Bsz, FPS_T>>>(pos);
    query_kernel<<<(Bsz * Mc) / QWARPS, QWARPS * 32>>>(pos, poss);
    mlp_kernel<<<152, MLP_T, SMEM_BYTES>>>(x, pos, W1, b1, W2, b2, out);
}